// round 10
// baseline (speedup 1.0000x reference)
#include <cuda_runtime.h>
#include <cuda_bf16.h>
#include <math.h>
#include <stdint.h>

#define BDIM   8
#define SEQ    1024
#define DMODEL 1024
#define NHEAD  16
#define DHEAD  64
#define QT     128

typedef __nv_bfloat16  bf16;
typedef __nv_bfloat162 bf162;

#define MROWS ((size_t)BDIM * SEQ)

// single dynamic-smem symbol shared by all kernels
extern __shared__ __align__(16) char dynsm[];

// ---- scratch (device globals; no runtime alloc) ----
__device__ bf16 g_xh[MROWS * DMODEL],        g_xl[MROWS * DMODEL];
__device__ bf16 g_wqt_h[(size_t)3*DMODEL*DMODEL], g_wqt_l[(size_t)3*DMODEL*DMODEL];
__device__ bf16 g_wot_h[(size_t)DMODEL*DMODEL],   g_wot_l[(size_t)DMODEL*DMODEL];
__device__ bf16 g_qkvh[MROWS * 3*DMODEL],    g_qkvl[MROWS * 3*DMODEL];
__device__ bf16 g_ctxh[MROWS * DMODEL],      g_ctxl[MROWS * DMODEL];

// ---------------- helpers ----------------
__device__ __forceinline__ uint32_t sptr(const void* p) {
    return (uint32_t)__cvta_generic_to_shared(p);
}
__device__ __forceinline__ void cpa16(void* s, const void* g) {
    asm volatile("cp.async.cg.shared.global [%0], [%1], 16;\n" :: "r"(sptr(s)), "l"(g));
}
__device__ __forceinline__ void cpa16s(uint32_t s, const void* g) {
    asm volatile("cp.async.cg.shared.global [%0], [%1], 16;\n" :: "r"(s), "l"(g));
}
__device__ __forceinline__ void cpcommit() { asm volatile("cp.async.commit_group;\n"); }
__device__ __forceinline__ void cpwait0()  { asm volatile("cp.async.wait_group 0;\n"); }
__device__ __forceinline__ void cpwait1()  { asm volatile("cp.async.wait_group 1;\n"); }
template<int N> __device__ __forceinline__ void cpwaitN() {
    asm volatile("cp.async.wait_group %0;\n" :: "n"(N));
}

__device__ __forceinline__ void ldsm4(uint32_t* r, const void* p) {
    asm volatile("ldmatrix.sync.aligned.m8n8.x4.shared.b16 {%0,%1,%2,%3}, [%4];\n"
        : "=r"(r[0]), "=r"(r[1]), "=r"(r[2]), "=r"(r[3]) : "r"(sptr(p)));
}
__device__ __forceinline__ void ldsm4s(uint32_t* r, uint32_t a) {
    asm volatile("ldmatrix.sync.aligned.m8n8.x4.shared.b16 {%0,%1,%2,%3}, [%4];\n"
        : "=r"(r[0]), "=r"(r[1]), "=r"(r[2]), "=r"(r[3]) : "r"(a));
}
__device__ __forceinline__ void ldsm4t(uint32_t* r, const void* p) {
    asm volatile("ldmatrix.sync.aligned.m8n8.x4.trans.shared.b16 {%0,%1,%2,%3}, [%4];\n"
        : "=r"(r[0]), "=r"(r[1]), "=r"(r[2]), "=r"(r[3]) : "r"(sptr(p)));
}
__device__ __forceinline__ void ldsm2s(uint32_t* r, uint32_t a) {
    asm volatile("ldmatrix.sync.aligned.m8n8.x2.shared.b16 {%0,%1}, [%2];\n"
        : "=r"(r[0]), "=r"(r[1]) : "r"(a));
}
__device__ __forceinline__ void mma16816(float* c, const uint32_t* a, const uint32_t* b) {
    asm volatile("mma.sync.aligned.m16n8k16.row.col.f32.bf16.bf16.f32 "
        "{%0,%1,%2,%3}, {%4,%5,%6,%7}, {%8,%9}, {%0,%1,%2,%3};\n"
        : "+f"(c[0]), "+f"(c[1]), "+f"(c[2]), "+f"(c[3])
        : "r"(a[0]), "r"(a[1]), "r"(a[2]), "r"(a[3]), "r"(b[0]), "r"(b[1]));
}
__device__ __forceinline__ void split1(float v, bf16& h, bf16& l) {
    h = __float2bfloat16_rn(v);
    l = __float2bfloat16_rn(v - __bfloat162float(h));
}
__device__ __forceinline__ uint32_t pack2(bf16 lo, bf16 hi) {
    return (uint32_t)__bfloat16_as_ushort(lo) | ((uint32_t)__bfloat16_as_ushort(hi) << 16);
}
__device__ __forceinline__ void split_pack2(float v0, float v1, uint32_t& ph, uint32_t& pl) {
    bf16 h0,l0,h1,l1;
    split1(v0,h0,l0); split1(v1,h1,l1);
    ph = pack2(h0,h1);
    pl = pack2(l0,l1);
}
// SW64 swizzle: XOR bits[5:4] with bits[8:7] (64B rows)
__device__ __forceinline__ uint32_t sw64(uint32_t off) {
    return off ^ ((off >> 3) & 0x30);
}
// 2^y via magic rounding + degree-5 poly (FMA pipe only, no MUFU). |y| < 30.
__device__ __forceinline__ float fexp2p(float y) {
    float t = y + 12582912.f;
    float n = t - 12582912.f;
    float f = y - n;
    float p = 0.00133335581f;
    p = fmaf(p, f, 0.00961812911f);
    p = fmaf(p, f, 0.05550410866f);
    p = fmaf(p, f, 0.24022650696f);
    p = fmaf(p, f, 0.69314718056f);
    p = fmaf(p, f, 1.0f);
    int e = (__float_as_int(t) - 0x4B400000 + 127) << 23;
    return __int_as_float(e) * p;
}
#define Y_SCALE 0.18033688011112042f   // 0.125 * log2(e)

// ---------------- converters ----------------
__global__ void split_kernel(const float* __restrict__ in,
                             bf16* __restrict__ oh, bf16* __restrict__ ol, int n4)
{
    int i = blockIdx.x * blockDim.x + threadIdx.x;
    if (i >= n4) return;
    float4 v = ((const float4*)in)[i];
    uint32_t ph0, pl0, ph1, pl1;
    split_pack2(v.x, v.y, ph0, pl0);
    split_pack2(v.z, v.w, ph1, pl1);
    ((uint32_t*)oh)[2*i]   = ph0;
    ((uint32_t*)oh)[2*i+1] = ph1;
    ((uint32_t*)ol)[2*i]   = pl0;
    ((uint32_t*)ol)[2*i+1] = pl1;
}

__global__ void transpose_split(const float* __restrict__ in,
                                bf16* __restrict__ oh, bf16* __restrict__ ol,
                                int K, int N)
{
    __shared__ float t[32][33];
    int k0 = blockIdx.y * 32, n0 = blockIdx.x * 32;
    int tx = threadIdx.x, ty = threadIdx.y;
#pragma unroll
    for (int i = 0; i < 4; i++)
        t[ty + 8*i][tx] = in[(size_t)(k0 + ty + 8*i) * N + n0 + tx];
    __syncthreads();
#pragma unroll
    for (int i = 0; i < 4; i++) {
        float v = t[tx][ty + 8*i];
        bf16 h, l; split1(v, h, l);
        size_t o = (size_t)(n0 + ty + 8*i) * K + k0 + tx;
        oh[o] = h; ol[o] = l;
    }
}

// ---------------- GEMM (bf16 split, 3-term), 3-stage pipeline, 2 CTAs/SM ----
#define GSTG 32768
__global__ __launch_bounds__(256, 2)
void mma_gemm(const bf16* __restrict__ Ah, const bf16* __restrict__ Al,
              const bf16* __restrict__ Bh, const bf16* __restrict__ Bl,
              float* __restrict__ Cf, bf16* __restrict__ Ch, bf16* __restrict__ Cl,
              const float* __restrict__ bias, int M, int N, int K)
{
    const uint32_t smbase = (sptr(dynsm) + 1023u) & ~1023u;

    const int tid  = threadIdx.x;
    const int lane = tid & 31, wid = tid >> 5;
    const int mw = wid >> 2, nw = wid & 3;
    const int bm = blockIdx.y * 128, bn = blockIdx.x * 128;

    float acc[4][4][4];
#pragma unroll
    for (int a = 0; a < 4; a++)
#pragma unroll
        for (int b = 0; b < 4; b++)
#pragma unroll
            for (int c = 0; c < 4; c++) acc[a][b][c] = 0.f;

    auto stage = [&](int st, int kc) {
        const int k0 = kc * 32;
        const uint32_t sb = smbase + st * GSTG;
#pragma unroll
        for (int i = 0; i < 2; i++) {
            int s = tid + i * 256;
            int r = s >> 2, c = (s & 3) * 8;
            uint32_t off = sw64((uint32_t)(r * 64 + c * 2));
            size_t ga = (size_t)(bm + r) * K + k0 + c;
            size_t gb = (size_t)(bn + r) * K + k0 + c;
            cpa16s(sb + off,         Ah + ga);
            cpa16s(sb +  8192 + off, Al + ga);
            cpa16s(sb + 16384 + off, Bh + gb);
            cpa16s(sb + 24576 + off, Bl + gb);
        }
        cpcommit();
    };

    const int NT = K / 32;
    stage(0, 0);
    stage(1, 1);

    for (int kt = 0; kt < NT; kt++) {
        const uint32_t sb = smbase + (kt % 3) * GSTG;
        if (kt + 1 < NT) cpwait1(); else cpwait0();
        __syncthreads();
        if (kt + 2 < NT) stage((kt + 2) % 3, kt + 2);

#pragma unroll
        for (int ks = 0; ks < 2; ks++) {
            uint32_t afh[4][4], afl[4][4], bfh[4][2], bfl[4][2];
#pragma unroll
            for (int mf = 0; mf < 4; mf++) {
                int row = mw*64 + mf*16 + (lane & 15);
                int col = ks*16 + (lane >> 4) * 8;
                uint32_t off = sw64((uint32_t)(row * 64 + col * 2));
                ldsm4s(afh[mf], sb + off);
                ldsm4s(afl[mf], sb + 8192 + off);
            }
#pragma unroll
            for (int nf = 0; nf < 4; nf++) {
                int li = lane & 15;
                int row = nw*32 + nf*8 + (li & 7);
                int col = ks*16 + (li >> 3) * 8;
                uint32_t off = sw64((uint32_t)(row * 64 + col * 2));
                ldsm2s(bfh[nf], sb + 16384 + off);
                ldsm2s(bfl[nf], sb + 24576 + off);
            }
#pragma unroll
            for (int mf = 0; mf < 4; mf++)
#pragma unroll
                for (int nf = 0; nf < 4; nf++)
                    mma16816(acc[mf][nf], afh[mf], bfh[nf]);
#pragma unroll
            for (int mf = 0; mf < 4; mf++)
#pragma unroll
                for (int nf = 0; nf < 4; nf++)
                    mma16816(acc[mf][nf], afh[mf], bfl[nf]);
#pragma unroll
            for (int mf = 0; mf < 4; mf++)
#pragma unroll
                for (int nf = 0; nf < 4; nf++)
                    mma16816(acc[mf][nf], afl[mf], bfh[nf]);
        }
    }

#pragma unroll
    for (int mf = 0; mf < 4; mf++)
#pragma unroll
        for (int nf = 0; nf < 4; nf++)
#pragma unroll
            for (int c = 0; c < 2; c++) {
                int row = bm + mw*64 + mf*16 + (lane >> 2) + c*8;
                int col = bn + nw*32 + nf*8  + 2*(lane & 3);
                float v0 = acc[mf][nf][2*c+0];
                float v1 = acc[mf][nf][2*c+1];
                if (bias) { v0 += bias[col]; v1 += bias[col+1]; }
                if (Cf) *(float2*)&Cf[(size_t)row * N + col] = make_float2(v0, v1);
                if (Ch) {
                    uint32_t ph, pl;
                    split_pack2(v0, v1, ph, pl);
                    *(uint32_t*)&Ch[(size_t)row * N + col] = ph;
                    *(uint32_t*)&Cl[(size_t)row * N + col] = pl;
                }
            }
}

// ---------------- one-pass attention, 2 CTAs/SM, split K/V commit groups ----
// grid (SEQ/128, B*H), 256 threads = 8 warps, each warp owns 16 query rows.
// Separate cp.async groups for K and V: QK waits only on K(kt); V(kt+1) loads
// overlap PV(kt) + QK(kt+1). Two barriers per kt preserve WAR ordering.
#define KBUF 4608   // 64*72 elements per K/V buffer
__global__ __launch_bounds__(256, 2)
void attn_one(const bf16* __restrict__ qh, const bf16* __restrict__ ql,
              const int* __restrict__ mask,
              float* __restrict__ attn,
              bf16* __restrict__ ctxh, bf16* __restrict__ ctxl)
{
    char* sm = dynsm;
    bf16*  sQh  = (bf16*)sm;                    // 128*72
    bf16*  sQl  = (bf16*)(sm + 18432);
    bf16*  sKb  = (bf16*)(sm + 36864);          // [2 st][2 hl][64*72]
    bf16*  sVb  = (bf16*)(sm + 73728);
    int*   smask = (int*)(sm + 110592);         // [2][64]
    float* lrec  = (float*)(sm + 111104);       // [128]

    const int tid = threadIdx.x, lane = tid & 31, w = tid >> 5;
    const int q0 = blockIdx.x * QT;
    const int bh = blockIdx.y, b = bh >> 4, h = bh & 15;
    const size_t RS = 3 * DMODEL;

    // group G0: Q tile
    for (int s = tid; s < 1024; s += 256) {
        int r = s >> 3, c = (s & 7) * 8;
        size_t g = (size_t)(b*SEQ + q0 + r) * RS + h*DHEAD + c;
        cpa16(&sQh[r*72 + c], qh + g);
        cpa16(&sQl[r*72 + c], ql + g);
    }
    cpcommit();

    auto stageK = [&](int st, int kt) {
        int k0 = kt * 64;
        if (tid < 64) smask[st*64 + tid] = mask[b*SEQ + k0 + tid];
#pragma unroll
        for (int i = 0; i < 2; i++) {
            int s = tid + i * 256;
            int r = s >> 3, c = (s & 7) * 8;
            size_t gk = (size_t)(b*SEQ + k0 + r) * RS + DMODEL + h*DHEAD + c;
            cpa16(&sKb[(st*2+0)*KBUF + r*72 + c], qh + gk);
            cpa16(&sKb[(st*2+1)*KBUF + r*72 + c], ql + gk);
        }
        cpcommit();
    };
    auto stageV = [&](int st, int kt) {
        int k0 = kt * 64;
#pragma unroll
        for (int i = 0; i < 2; i++) {
            int s = tid + i * 256;
            int r = s >> 3, c = (s & 7) * 8;
            size_t gv = (size_t)(b*SEQ + k0 + r) * RS + 2*DMODEL + h*DHEAD + c;
            cpa16(&sVb[(st*2+0)*KBUF + r*72 + c], qh + gv);
            cpa16(&sVb[(st*2+1)*KBUF + r*72 + c], ql + gv);
        }
        cpcommit();
    };

    stageK(0, 0);   // G1
    stageV(0, 0);   // G2

    float oacc[8][4];
#pragma unroll
    for (int nf = 0; nf < 8; nf++)
#pragma unroll
        for (int c = 0; c < 4; c++) oacc[nf][c] = 0.f;
    float rs0 = 0.f, rs1 = 0.f;

    const int rlo = lane >> 2, qq = lane & 3;
    const int g8 = lane >> 3;
    const size_t abase = ((size_t)bh * SEQ + q0) * SEQ;

    for (int kt = 0; kt < 16; kt++) {
        int st = kt & 1;
        if (kt + 1 < 16) stageK(st ^ 1, kt + 1);
        // wait: Q (first iter) and K(kt) arrived; pending <= {V(kt), K(kt+1)}
        if (kt + 1 < 16) cpwaitN<2>(); else cpwaitN<1>();
        __syncthreads();

        // ---- S = Q K^T (per-warp m16 x n64) ----
        float sacc[8][4];
#pragma unroll
        for (int nf = 0; nf < 8; nf++)
#pragma unroll
            for (int c = 0; c < 4; c++) sacc[nf][c] = 0.f;

#pragma unroll
        for (int ks = 0; ks < 4; ks++) {
            uint32_t q4h[4], q4l[4];
            int qoff = (w*16 + (lane & 15)) * 72 + ks*16 + (lane >> 4) * 8;
            ldsm4(q4h, &sQh[qoff]);
            ldsm4(q4l, &sQl[qoff]);
#pragma unroll
            for (int p = 0; p < 4; p++) {
                int off = (p*16 + (g8 & 1)*8 + (lane & 7)) * 72 + ks*16 + (g8 >> 1) * 8;
                uint32_t r4[4], s4[4];
                ldsm4(r4, &sKb[(st*2+0)*KBUF + off]);
                ldsm4(s4, &sKb[(st*2+1)*KBUF + off]);
                uint32_t b0[2] = {r4[0], r4[2]}, b1[2] = {r4[1], r4[3]};
                uint32_t c0[2] = {s4[0], s4[2]}, c1[2] = {s4[1], s4[3]};
                mma16816(sacc[2*p],   q4h, b0);
                mma16816(sacc[2*p+1], q4h, b1);
                mma16816(sacc[2*p],   q4h, c0);
                mma16816(sacc[2*p+1], q4h, c1);
                mma16816(sacc[2*p],   q4l, b0);
                mma16816(sacc[2*p+1], q4l, b1);
            }
        }

        // ---- exp (poly), mask, store unnormalized p in place ----
#pragma unroll
        for (int nf = 0; nf < 8; nf++) {
            int c0i = nf*8 + 2*qq;
            int m0 = smask[st*64 + c0i];
            int m1 = smask[st*64 + c0i + 1];
            float e0 = m0 ? fexp2p(sacc[nf][0] * Y_SCALE) : 0.f;
            float e1 = m1 ? fexp2p(sacc[nf][1] * Y_SCALE) : 0.f;
            float e2 = m0 ? fexp2p(sacc[nf][2] * Y_SCALE) : 0.f;
            float e3 = m1 ? fexp2p(sacc[nf][3] * Y_SCALE) : 0.f;
            sacc[nf][0] = e0; sacc[nf][1] = e1; sacc[nf][2] = e2; sacc[nf][3] = e3;
            rs0 += e0 + e1;
            rs1 += e2 + e3;
            size_t a0 = abase + (size_t)(w*16 + rlo) * SEQ + kt*64 + c0i;
            *(float2*)&attn[a0]           = make_float2(e0, e1);
            *(float2*)&attn[a0 + 8*SEQ]   = make_float2(e2, e3);
        }

        if (kt + 1 < 16) stageV(st ^ 1, kt + 1);
        // wait: V(kt) arrived; pending <= {K(kt+1), V(kt+1)}
        if (kt + 1 < 16) cpwaitN<2>(); else cpwaitN<0>();
        __syncthreads();

        // ---- O += P @ V ----
#pragma unroll
        for (int pk = 0; pk < 4; pk++) {
            uint32_t ah[4], al[4];
            split_pack2(sacc[2*pk][0],   sacc[2*pk][1],   ah[0], al[0]);
            split_pack2(sacc[2*pk][2],   sacc[2*pk][3],   ah[1], al[1]);
            split_pack2(sacc[2*pk+1][0], sacc[2*pk+1][1], ah[2], al[2]);
            split_pack2(sacc[2*pk+1][2], sacc[2*pk+1][3], ah[3], al[3]);
#pragma unroll
            for (int p = 0; p < 4; p++) {
                int off = (pk*16 + (g8 & 1)*8 + (lane & 7)) * 72 + (2*p + (g8 >> 1)) * 8;
                uint32_t r4[4], s4[4];
                ldsm4t(r4, &sVb[(st*2+0)*KBUF + off]);
                ldsm4t(s4, &sVb[(st*2+1)*KBUF + off]);
                uint32_t v0[2] = {r4[0], r4[1]}, v1[2] = {r4[2], r4[3]};
                uint32_t u0[2] = {s4[0], s4[1]}, u1[2] = {s4[2], s4[3]};
                mma16816(oacc[2*p],   ah, v0);
                mma16816(oacc[2*p+1], ah, v1);
                mma16816(oacc[2*p],   ah, u0);
                mma16816(oacc[2*p+1], ah, u1);
                mma16816(oacc[2*p],   al, v0);
                mma16816(oacc[2*p+1], al, v1);
            }
        }
    }

    // ---- finalize: l, ctx, normalize epilogue ----
    rs0 += __shfl_xor_sync(0xffffffffu, rs0, 1);
    rs0 += __shfl_xor_sync(0xffffffffu, rs0, 2);
    rs1 += __shfl_xor_sync(0xffffffffu, rs1, 1);
    rs1 += __shfl_xor_sync(0xffffffffu, rs1, 2);
    float ri0 = 1.f / rs0, ri1 = 1.f / rs1;
    if ((lane & 3) == 0) {
        lrec[w*16 + rlo]     = ri0;
        lrec[w*16 + rlo + 8] = ri1;
    }

    const size_t row0 = (size_t)(b*SEQ + q0 + w*16 + rlo);
#pragma unroll
    for (int nf = 0; nf < 8; nf++) {
        int col = h*DHEAD + nf*8 + 2*qq;
        uint32_t hp, lp;
        split_pack2(oacc[nf][0] * ri0, oacc[nf][1] * ri0, hp, lp);
        *(uint32_t*)&ctxh[row0*DMODEL + col] = hp;
        *(uint32_t*)&ctxl[row0*DMODEL + col] = lp;
        split_pack2(oacc[nf][2] * ri1, oacc[nf][3] * ri1, hp, lp);
        *(uint32_t*)&ctxh[(row0+8)*DMODEL + col] = hp;
        *(uint32_t*)&ctxl[(row0+8)*DMODEL + col] = lp;
    }

    __syncthreads();   // lrec visible + all attn stores in-block visible

    // normalize this block's attn region (L2-hot re-read)
    for (int s = tid; s < QT * 256; s += 256) {
        int r = s >> 8, c = (s & 255) * 4;
        float sc = lrec[r];
        float4* p = (float4*)(attn + abase + (size_t)r * SEQ + c);
        float4 v = *p;
        v.x *= sc; v.y *= sc; v.z *= sc; v.w *= sc;
        *p = v;
    }
}

// ---------------- launcher ----------------
extern "C" void kernel_launch(void* const* d_in, const int* in_sizes, int n_in,
                              void* d_out, int out_size)
{
    const float* x     = (const float*)d_in[0];
    const int*   mask  = (const int*)d_in[1];
    const float* w_qkv = (const float*)d_in[2];
    const float* w_out = (const float*)d_in[3];
    const float* b_out = (const float*)d_in[4];

    float* out  = (float*)d_out;
    float* attn = out + MROWS * DMODEL;

    bf16 *xh, *xl, *wqh, *wql, *woh, *wol, *qkvh, *qkvl, *ctxh, *ctxl;
    cudaGetSymbolAddress((void**)&xh,  g_xh);  cudaGetSymbolAddress((void**)&xl,  g_xl);
    cudaGetSymbolAddress((void**)&wqh, g_wqt_h); cudaGetSymbolAddress((void**)&wql, g_wqt_l);
    cudaGetSymbolAddress((void**)&woh, g_wot_h); cudaGetSymbolAddress((void**)&wol, g_wot_l);
    cudaGetSymbolAddress((void**)&qkvh, g_qkvh); cudaGetSymbolAddress((void**)&qkvl, g_qkvl);
    cudaGetSymbolAddress((void**)&ctxh, g_ctxh); cudaGetSymbolAddress((void**)&ctxl, g_ctxl);

    cudaFuncSetAttribute(mma_gemm, cudaFuncAttributeMaxDynamicSharedMemorySize, 99328);
    cudaFuncSetAttribute(attn_one, cudaFuncAttributeMaxDynamicSharedMemorySize, 111616);

    {
        int n4 = (int)(MROWS * DMODEL / 4);
        split_kernel<<<(n4 + 255) / 256, 256>>>(x, xh, xl, n4);
    }
    transpose_split<<<dim3(3*DMODEL/32, DMODEL/32), dim3(32,8)>>>(w_qkv, wqh, wql, DMODEL, 3*DMODEL);
    transpose_split<<<dim3(DMODEL/32,   DMODEL/32), dim3(32,8)>>>(w_out, woh, wol, DMODEL, DMODEL);

    mma_gemm<<<dim3(3*DMODEL/128, (int)(MROWS/128)), 256, 99328>>>(
        xh, xl, wqh, wql, nullptr, qkvh, qkvl, nullptr,
        (int)MROWS, 3*DMODEL, DMODEL);

    attn_one<<<dim3(SEQ/QT, BDIM*NHEAD), 256, 111616>>>(
        qkvh, qkvl, mask, attn, ctxh, ctxl);

    mma_gemm<<<dim3(DMODEL/128, (int)(MROWS/128)), 256, 99328>>>(
        ctxh, ctxl, woh, wol, out, nullptr, nullptr, b_out,
        (int)MROWS, DMODEL, DMODEL);
}

// round 11
// speedup vs baseline: 1.0351x; 1.0351x over previous
#include <cuda_runtime.h>
#include <cuda_bf16.h>
#include <math.h>
#include <stdint.h>

#define BDIM   8
#define SEQ    1024
#define DMODEL 1024
#define NHEAD  16
#define DHEAD  64
#define QT     128

typedef __nv_bfloat16  bf16;
typedef __nv_bfloat162 bf162;

#define MROWS ((size_t)BDIM * SEQ)

// single dynamic-smem symbol shared by all kernels
extern __shared__ __align__(16) char dynsm[];

// ---- scratch (device globals; no runtime alloc) ----
__device__ bf16 g_xh[MROWS * DMODEL],        g_xl[MROWS * DMODEL];
__device__ bf16 g_wqt_h[(size_t)3*DMODEL*DMODEL], g_wqt_l[(size_t)3*DMODEL*DMODEL];
__device__ bf16 g_wot_h[(size_t)DMODEL*DMODEL],   g_wot_l[(size_t)DMODEL*DMODEL];
__device__ bf16 g_qkvh[MROWS * 3*DMODEL],    g_qkvl[MROWS * 3*DMODEL];
__device__ bf16 g_ctxh[MROWS * DMODEL],      g_ctxl[MROWS * DMODEL];

// ---------------- helpers ----------------
__device__ __forceinline__ uint32_t sptr(const void* p) {
    return (uint32_t)__cvta_generic_to_shared(p);
}
__device__ __forceinline__ void cpa16(void* s, const void* g) {
    asm volatile("cp.async.cg.shared.global [%0], [%1], 16;\n" :: "r"(sptr(s)), "l"(g));
}
__device__ __forceinline__ void cpa16s(uint32_t s, const void* g) {
    asm volatile("cp.async.cg.shared.global [%0], [%1], 16;\n" :: "r"(s), "l"(g));
}
__device__ __forceinline__ void cpcommit() { asm volatile("cp.async.commit_group;\n"); }
__device__ __forceinline__ void cpwait0()  { asm volatile("cp.async.wait_group 0;\n"); }
__device__ __forceinline__ void cpwait1()  { asm volatile("cp.async.wait_group 1;\n"); }

__device__ __forceinline__ void ldsm4(uint32_t* r, const void* p) {
    asm volatile("ldmatrix.sync.aligned.m8n8.x4.shared.b16 {%0,%1,%2,%3}, [%4];\n"
        : "=r"(r[0]), "=r"(r[1]), "=r"(r[2]), "=r"(r[3]) : "r"(sptr(p)));
}
__device__ __forceinline__ void ldsm4s(uint32_t* r, uint32_t a) {
    asm volatile("ldmatrix.sync.aligned.m8n8.x4.shared.b16 {%0,%1,%2,%3}, [%4];\n"
        : "=r"(r[0]), "=r"(r[1]), "=r"(r[2]), "=r"(r[3]) : "r"(a));
}
__device__ __forceinline__ void ldsm4t(uint32_t* r, const void* p) {
    asm volatile("ldmatrix.sync.aligned.m8n8.x4.trans.shared.b16 {%0,%1,%2,%3}, [%4];\n"
        : "=r"(r[0]), "=r"(r[1]), "=r"(r[2]), "=r"(r[3]) : "r"(sptr(p)));
}
__device__ __forceinline__ void ldsm2s(uint32_t* r, uint32_t a) {
    asm volatile("ldmatrix.sync.aligned.m8n8.x2.shared.b16 {%0,%1}, [%2];\n"
        : "=r"(r[0]), "=r"(r[1]) : "r"(a));
}
__device__ __forceinline__ void mma16816(float* c, const uint32_t* a, const uint32_t* b) {
    asm volatile("mma.sync.aligned.m16n8k16.row.col.f32.bf16.bf16.f32 "
        "{%0,%1,%2,%3}, {%4,%5,%6,%7}, {%8,%9}, {%0,%1,%2,%3};\n"
        : "+f"(c[0]), "+f"(c[1]), "+f"(c[2]), "+f"(c[3])
        : "r"(a[0]), "r"(a[1]), "r"(a[2]), "r"(a[3]), "r"(b[0]), "r"(b[1]));
}
__device__ __forceinline__ uint32_t prmt(uint32_t a, uint32_t b, uint32_t sel) {
    uint32_t d;
    asm("prmt.b32 %0, %1, %2, %3;" : "=r"(d) : "r"(a), "r"(b), "r"(sel));
    return d;
}
// rn-split (used by converters for max accuracy)
__device__ __forceinline__ void split1(float v, bf16& h, bf16& l) {
    h = __float2bfloat16_rn(v);
    l = __float2bfloat16_rn(v - __bfloat162float(h));
}
__device__ __forceinline__ uint32_t pack2(bf16 lo, bf16 hi) {
    return (uint32_t)__bfloat16_as_ushort(lo) | ((uint32_t)__bfloat16_as_ushort(hi) << 16);
}
__device__ __forceinline__ void split_pack2_rn(float v0, float v1, uint32_t& ph, uint32_t& pl) {
    bf16 h0,l0,h1,l1;
    split1(v0,h0,l0); split1(v1,h1,l1);
    ph = pack2(h0,h1);
    pl = pack2(l0,l1);
}
// FAST split: h = truncate-to-bf16 (top 16 bits), l = v - h (exact).
// hi-pair built with one PRMT; lo-pair with one cvt.rn.bf16x2.
__device__ __forceinline__ void split_pack2(float v0, float v1, uint32_t& ph, uint32_t& pl) {
    uint32_t u0 = __float_as_uint(v0), u1 = __float_as_uint(v1);
    ph = prmt(u0, u1, 0x7632);                 // {u1.hi16, u0.hi16}
    float h0 = __uint_as_float(u0 & 0xFFFF0000u);
    float h1 = __uint_as_float(u1 & 0xFFFF0000u);
    float l0 = v0 - h0, l1 = v1 - h1;
    asm("cvt.rn.bf16x2.f32 %0, %1, %2;" : "=r"(pl) : "f"(l1), "f"(l0));  // lo=l0, hi=l1
}
// SW64 swizzle: XOR bits[5:4] with bits[8:7] (64B rows)
__device__ __forceinline__ uint32_t sw64(uint32_t off) {
    return off ^ ((off >> 3) & 0x30);
}
// exp(s*0.125) = 2^(s*YS) via magic rounding + degree-5 poly. Y_SCALE folded in.
#define Y_SCALE 0.18033688011112042f   // 0.125 * log2(e)
__device__ __forceinline__ float fexp2s(float s) {
    float t = fmaf(s, Y_SCALE, 12582912.f);     // 2^23 + 2^22 magic (RN)
    float n = t - 12582912.f;
    float f = fmaf(s, Y_SCALE, -n);
    float p = 0.00133335581f;
    p = fmaf(p, f, 0.00961812911f);
    p = fmaf(p, f, 0.05550410866f);
    p = fmaf(p, f, 0.24022650696f);
    p = fmaf(p, f, 0.69314718056f);
    p = fmaf(p, f, 1.0f);
    int e = (__float_as_int(t) - 0x4B400000 + 127) << 23;
    return __int_as_float(e) * p;
}

// ---------------- converters ----------------
__global__ void split_kernel(const float* __restrict__ in,
                             bf16* __restrict__ oh, bf16* __restrict__ ol, int n4)
{
    int i = blockIdx.x * blockDim.x + threadIdx.x;
    if (i >= n4) return;
    float4 v = ((const float4*)in)[i];
    uint32_t ph0, pl0, ph1, pl1;
    split_pack2_rn(v.x, v.y, ph0, pl0);
    split_pack2_rn(v.z, v.w, ph1, pl1);
    ((uint32_t*)oh)[2*i]   = ph0;
    ((uint32_t*)oh)[2*i+1] = ph1;
    ((uint32_t*)ol)[2*i]   = pl0;
    ((uint32_t*)ol)[2*i+1] = pl1;
}

__global__ void transpose_split(const float* __restrict__ in,
                                bf16* __restrict__ oh, bf16* __restrict__ ol,
                                int K, int N)
{
    __shared__ float t[32][33];
    int k0 = blockIdx.y * 32, n0 = blockIdx.x * 32;
    int tx = threadIdx.x, ty = threadIdx.y;
#pragma unroll
    for (int i = 0; i < 4; i++)
        t[ty + 8*i][tx] = in[(size_t)(k0 + ty + 8*i) * N + n0 + tx];
    __syncthreads();
#pragma unroll
    for (int i = 0; i < 4; i++) {
        float v = t[tx][ty + 8*i];
        bf16 h, l; split1(v, h, l);
        size_t o = (size_t)(n0 + ty + 8*i) * K + k0 + tx;
        oh[o] = h; ol[o] = l;
    }
}

// ---------------- GEMM (bf16 split, 3-term), 3-stage pipeline, 2 CTAs/SM ----
#define GSTG 32768
__global__ __launch_bounds__(256, 2)
void mma_gemm(const bf16* __restrict__ Ah, const bf16* __restrict__ Al,
              const bf16* __restrict__ Bh, const bf16* __restrict__ Bl,
              float* __restrict__ Cf, bf16* __restrict__ Ch, bf16* __restrict__ Cl,
              const float* __restrict__ bias, int M, int N, int K)
{
    const uint32_t smbase = (sptr(dynsm) + 1023u) & ~1023u;

    const int tid  = threadIdx.x;
    const int lane = tid & 31, wid = tid >> 5;
    const int mw = wid >> 2, nw = wid & 3;
    const int bm = blockIdx.y * 128, bn = blockIdx.x * 128;

    float acc[4][4][4];
#pragma unroll
    for (int a = 0; a < 4; a++)
#pragma unroll
        for (int b = 0; b < 4; b++)
#pragma unroll
            for (int c = 0; c < 4; c++) acc[a][b][c] = 0.f;

    auto stage = [&](int st, int kc) {
        const int k0 = kc * 32;
        const uint32_t sb = smbase + st * GSTG;
#pragma unroll
        for (int i = 0; i < 2; i++) {
            int s = tid + i * 256;
            int r = s >> 2, c = (s & 3) * 8;
            uint32_t off = sw64((uint32_t)(r * 64 + c * 2));
            size_t ga = (size_t)(bm + r) * K + k0 + c;
            size_t gb = (size_t)(bn + r) * K + k0 + c;
            cpa16s(sb + off,         Ah + ga);
            cpa16s(sb +  8192 + off, Al + ga);
            cpa16s(sb + 16384 + off, Bh + gb);
            cpa16s(sb + 24576 + off, Bl + gb);
        }
        cpcommit();
    };

    const int NT = K / 32;
    stage(0, 0);
    stage(1, 1);

    for (int kt = 0; kt < NT; kt++) {
        const uint32_t sb = smbase + (kt % 3) * GSTG;
        if (kt + 1 < NT) cpwait1(); else cpwait0();
        __syncthreads();
        if (kt + 2 < NT) stage((kt + 2) % 3, kt + 2);

#pragma unroll
        for (int ks = 0; ks < 2; ks++) {
            uint32_t afh[4][4], afl[4][4], bfh[4][2], bfl[4][2];
#pragma unroll
            for (int mf = 0; mf < 4; mf++) {
                int row = mw*64 + mf*16 + (lane & 15);
                int col = ks*16 + (lane >> 4) * 8;
                uint32_t off = sw64((uint32_t)(row * 64 + col * 2));
                ldsm4s(afh[mf], sb + off);
                ldsm4s(afl[mf], sb + 8192 + off);
            }
#pragma unroll
            for (int nf = 0; nf < 4; nf++) {
                int li = lane & 15;
                int row = nw*32 + nf*8 + (li & 7);
                int col = ks*16 + (li >> 3) * 8;
                uint32_t off = sw64((uint32_t)(row * 64 + col * 2));
                ldsm2s(bfh[nf], sb + 16384 + off);
                ldsm2s(bfl[nf], sb + 24576 + off);
            }
#pragma unroll
            for (int mf = 0; mf < 4; mf++)
#pragma unroll
                for (int nf = 0; nf < 4; nf++)
                    mma16816(acc[mf][nf], afh[mf], bfh[nf]);
#pragma unroll
            for (int mf = 0; mf < 4; mf++)
#pragma unroll
                for (int nf = 0; nf < 4; nf++)
                    mma16816(acc[mf][nf], afh[mf], bfl[nf]);
#pragma unroll
            for (int mf = 0; mf < 4; mf++)
#pragma unroll
                for (int nf = 0; nf < 4; nf++)
                    mma16816(acc[mf][nf], afl[mf], bfh[nf]);
        }
    }

#pragma unroll
    for (int mf = 0; mf < 4; mf++)
#pragma unroll
        for (int nf = 0; nf < 4; nf++)
#pragma unroll
            for (int c = 0; c < 2; c++) {
                int row = bm + mw*64 + mf*16 + (lane >> 2) + c*8;
                int col = bn + nw*32 + nf*8  + 2*(lane & 3);
                float v0 = acc[mf][nf][2*c+0];
                float v1 = acc[mf][nf][2*c+1];
                if (bias) { v0 += bias[col]; v1 += bias[col+1]; }
                if (Cf) *(float2*)&Cf[(size_t)row * N + col] = make_float2(v0, v1);
                if (Ch) {
                    uint32_t ph, pl;
                    split_pack2(v0, v1, ph, pl);
                    *(uint32_t*)&Ch[(size_t)row * N + col] = ph;
                    *(uint32_t*)&Cl[(size_t)row * N + col] = pl;
                }
            }
}

// ---------------- one-pass attention, 2 CTAs/SM (R9 loop structure) --------
#define KBUF 4608   // 64*72 elements per K/V buffer
__global__ __launch_bounds__(256, 2)
void attn_one(const bf16* __restrict__ qh, const bf16* __restrict__ ql,
              const int* __restrict__ mask,
              float* __restrict__ attn,
              bf16* __restrict__ ctxh, bf16* __restrict__ ctxl)
{
    char* sm = dynsm;
    bf16*  sQh  = (bf16*)sm;                    // 128*72
    bf16*  sQl  = (bf16*)(sm + 18432);
    bf16*  sKb  = (bf16*)(sm + 36864);          // [2 st][2 hl][64*72]
    bf16*  sVb  = (bf16*)(sm + 73728);
    int*   smask = (int*)(sm + 110592);         // [2][64]
    float* lrec  = (float*)(sm + 111104);       // [128]

    const int tid = threadIdx.x, lane = tid & 31, w = tid >> 5;
    const int q0 = blockIdx.x * QT;
    const int bh = blockIdx.y, b = bh >> 4, h = bh & 15;
    const size_t RS = 3 * DMODEL;

    for (int s = tid; s < 1024; s += 256) {
        int r = s >> 3, c = (s & 7) * 8;
        size_t g = (size_t)(b*SEQ + q0 + r) * RS + h*DHEAD + c;
        cpa16(&sQh[r*72 + c], qh + g);
        cpa16(&sQl[r*72 + c], ql + g);
    }
    cpcommit();

    auto stageKV = [&](int st, int kt) {
        int k0 = kt * 64;
        if (tid < 64) smask[st*64 + tid] = mask[b*SEQ + k0 + tid];
        for (int s = tid; s < 512; s += 256) {
            int r = s >> 3, c = (s & 7) * 8;
            size_t gk = (size_t)(b*SEQ + k0 + r) * RS + DMODEL + h*DHEAD + c;
            size_t gv = gk + DMODEL;
            cpa16(&sKb[(st*2+0)*KBUF + r*72 + c], qh + gk);
            cpa16(&sKb[(st*2+1)*KBUF + r*72 + c], ql + gk);
            cpa16(&sVb[(st*2+0)*KBUF + r*72 + c], qh + gv);
            cpa16(&sVb[(st*2+1)*KBUF + r*72 + c], ql + gv);
        }
        cpcommit();
    };

    stageKV(0, 0);
    cpwait0();
    __syncthreads();

    float oacc[8][4];
#pragma unroll
    for (int nf = 0; nf < 8; nf++)
#pragma unroll
        for (int c = 0; c < 4; c++) oacc[nf][c] = 0.f;
    float rs0 = 0.f, rs1 = 0.f;

    const int rlo = lane >> 2, qq = lane & 3;
    const int g8 = lane >> 3;
    const size_t abase = ((size_t)bh * SEQ + q0) * SEQ;

    for (int kt = 0; kt < 16; kt++) {
        int st = kt & 1;
        if (kt) { cpwait0(); __syncthreads(); }
        if (kt + 1 < 16) stageKV(st ^ 1, kt + 1);

        float sacc[8][4];
#pragma unroll
        for (int nf = 0; nf < 8; nf++)
#pragma unroll
            for (int c = 0; c < 4; c++) sacc[nf][c] = 0.f;

#pragma unroll
        for (int ks = 0; ks < 4; ks++) {
            uint32_t q4h[4], q4l[4];
            int qoff = (w*16 + (lane & 15)) * 72 + ks*16 + (lane >> 4) * 8;
            ldsm4(q4h, &sQh[qoff]);
            ldsm4(q4l, &sQl[qoff]);
#pragma unroll
            for (int p = 0; p < 4; p++) {
                int off = (p*16 + (g8 & 1)*8 + (lane & 7)) * 72 + ks*16 + (g8 >> 1) * 8;
                uint32_t r4[4], s4[4];
                ldsm4(r4, &sKb[(st*2+0)*KBUF + off]);
                ldsm4(s4, &sKb[(st*2+1)*KBUF + off]);
                uint32_t b0[2] = {r4[0], r4[2]}, b1[2] = {r4[1], r4[3]};
                uint32_t c0[2] = {s4[0], s4[2]}, c1[2] = {s4[1], s4[3]};
                mma16816(sacc[2*p],   q4h, b0);
                mma16816(sacc[2*p+1], q4h, b1);
                mma16816(sacc[2*p],   q4h, c0);
                mma16816(sacc[2*p+1], q4h, c1);
                mma16816(sacc[2*p],   q4l, b0);
                mma16816(sacc[2*p+1], q4l, b1);
            }
        }

#pragma unroll
        for (int nf = 0; nf < 8; nf++) {
            int c0i = nf*8 + 2*qq;
            int m0 = smask[st*64 + c0i];
            int m1 = smask[st*64 + c0i + 1];
            float e0 = m0 ? fexp2s(sacc[nf][0]) : 0.f;
            float e1 = m1 ? fexp2s(sacc[nf][1]) : 0.f;
            float e2 = m0 ? fexp2s(sacc[nf][2]) : 0.f;
            float e3 = m1 ? fexp2s(sacc[nf][3]) : 0.f;
            sacc[nf][0] = e0; sacc[nf][1] = e1; sacc[nf][2] = e2; sacc[nf][3] = e3;
            rs0 += e0 + e1;
            rs1 += e2 + e3;
            size_t a0 = abase + (size_t)(w*16 + rlo) * SEQ + kt*64 + c0i;
            *(float2*)&attn[a0]           = make_float2(e0, e1);
            *(float2*)&attn[a0 + 8*SEQ]   = make_float2(e2, e3);
        }

#pragma unroll
        for (int pk = 0; pk < 4; pk++) {
            uint32_t ah[4], al[4];
            split_pack2(sacc[2*pk][0],   sacc[2*pk][1],   ah[0], al[0]);
            split_pack2(sacc[2*pk][2],   sacc[2*pk][3],   ah[1], al[1]);
            split_pack2(sacc[2*pk+1][0], sacc[2*pk+1][1], ah[2], al[2]);
            split_pack2(sacc[2*pk+1][2], sacc[2*pk+1][3], ah[3], al[3]);
#pragma unroll
            for (int p = 0; p < 4; p++) {
                int off = (pk*16 + (g8 & 1)*8 + (lane & 7)) * 72 + (2*p + (g8 >> 1)) * 8;
                uint32_t r4[4], s4[4];
                ldsm4t(r4, &sVb[(st*2+0)*KBUF + off]);
                ldsm4t(s4, &sVb[(st*2+1)*KBUF + off]);
                uint32_t v0[2] = {r4[0], r4[1]}, v1[2] = {r4[2], r4[3]};
                uint32_t u0[2] = {s4[0], s4[1]}, u1[2] = {s4[2], s4[3]};
                mma16816(oacc[2*p],   ah, v0);
                mma16816(oacc[2*p+1], ah, v1);
                mma16816(oacc[2*p],   ah, u0);
                mma16816(oacc[2*p+1], ah, u1);
                mma16816(oacc[2*p],   al, v0);
                mma16816(oacc[2*p+1], al, v1);
            }
        }
    }

    rs0 += __shfl_xor_sync(0xffffffffu, rs0, 1);
    rs0 += __shfl_xor_sync(0xffffffffu, rs0, 2);
    rs1 += __shfl_xor_sync(0xffffffffu, rs1, 1);
    rs1 += __shfl_xor_sync(0xffffffffu, rs1, 2);
    float ri0 = 1.f / rs0, ri1 = 1.f / rs1;
    if ((lane & 3) == 0) {
        lrec[w*16 + rlo]     = ri0;
        lrec[w*16 + rlo + 8] = ri1;
    }

    const size_t row0 = (size_t)(b*SEQ + q0 + w*16 + rlo);
#pragma unroll
    for (int nf = 0; nf < 8; nf++) {
        int col = h*DHEAD + nf*8 + 2*qq;
        uint32_t hp, lp;
        split_pack2(oacc[nf][0] * ri0, oacc[nf][1] * ri0, hp, lp);
        *(uint32_t*)&ctxh[row0*DMODEL + col] = hp;
        *(uint32_t*)&ctxl[row0*DMODEL + col] = lp;
        split_pack2(oacc[nf][2] * ri1, oacc[nf][3] * ri1, hp, lp);
        *(uint32_t*)&ctxh[(row0+8)*DMODEL + col] = hp;
        *(uint32_t*)&ctxl[(row0+8)*DMODEL + col] = lp;
    }

    __syncthreads();   // lrec visible + all attn stores in-block visible

    for (int s = tid; s < QT * 256; s += 256) {
        int r = s >> 8, c = (s & 255) * 4;
        float sc = lrec[r];
        float4* p = (float4*)(attn + abase + (size_t)r * SEQ + c);
        float4 v = *p;
        v.x *= sc; v.y *= sc; v.z *= sc; v.w *= sc;
        *p = v;
    }
}

// ---------------- launcher ----------------
extern "C" void kernel_launch(void* const* d_in, const int* in_sizes, int n_in,
                              void* d_out, int out_size)
{
    const float* x     = (const float*)d_in[0];
    const int*   mask  = (const int*)d_in[1];
    const float* w_qkv = (const float*)d_in[2];
    const float* w_out = (const float*)d_in[3];
    const float* b_out = (const float*)d_in[4];

    float* out  = (float*)d_out;
    float* attn = out + MROWS * DMODEL;

    bf16 *xh, *xl, *wqh, *wql, *woh, *wol, *qkvh, *qkvl, *ctxh, *ctxl;
    cudaGetSymbolAddress((void**)&xh,  g_xh);  cudaGetSymbolAddress((void**)&xl,  g_xl);
    cudaGetSymbolAddress((void**)&wqh, g_wqt_h); cudaGetSymbolAddress((void**)&wql, g_wqt_l);
    cudaGetSymbolAddress((void**)&woh, g_wot_h); cudaGetSymbolAddress((void**)&wol, g_wot_l);
    cudaGetSymbolAddress((void**)&qkvh, g_qkvh); cudaGetSymbolAddress((void**)&qkvl, g_qkvl);
    cudaGetSymbolAddress((void**)&ctxh, g_ctxh); cudaGetSymbolAddress((void**)&ctxl, g_ctxl);

    cudaFuncSetAttribute(mma_gemm, cudaFuncAttributeMaxDynamicSharedMemorySize, 99328);
    cudaFuncSetAttribute(attn_one, cudaFuncAttributeMaxDynamicSharedMemorySize, 111616);

    {
        int n4 = (int)(MROWS * DMODEL / 4);
        split_kernel<<<(n4 + 255) / 256, 256>>>(x, xh, xl, n4);
    }
    transpose_split<<<dim3(3*DMODEL/32, DMODEL/32), dim3(32,8)>>>(w_qkv, wqh, wql, DMODEL, 3*DMODEL);
    transpose_split<<<dim3(DMODEL/32,   DMODEL/32), dim3(32,8)>>>(w_out, woh, wol, DMODEL, DMODEL);

    mma_gemm<<<dim3(3*DMODEL/128, (int)(MROWS/128)), 256, 99328>>>(
        xh, xl, wqh, wql, nullptr, qkvh, qkvl, nullptr,
        (int)MROWS, 3*DMODEL, DMODEL);

    attn_one<<<dim3(SEQ/QT, BDIM*NHEAD), 256, 111616>>>(
        qkvh, qkvl, mask, attn, ctxh, ctxl);

    mma_gemm<<<dim3(DMODEL/128, (int)(MROWS/128)), 256, 99328>>>(
        ctxh, ctxl, woh, wol, out, nullptr, nullptr, b_out,
        (int)MROWS, DMODEL, DMODEL);
}

// round 12
// speedup vs baseline: 1.2696x; 1.2266x over previous
#include <cuda_runtime.h>
#include <cuda_fp16.h>
#include <math.h>
#include <stdint.h>

#define BDIM   8
#define SEQ    1024
#define DMODEL 1024
#define NHEAD  16
#define DHEAD  64
#define QT     128

typedef __half  hf16;

#define MROWS ((size_t)BDIM * SEQ)

// single dynamic-smem symbol shared by all kernels
extern __shared__ __align__(16) char dynsm[];

// ---- scratch (device globals; no runtime alloc) ----
__device__ hf16 g_xh[MROWS * DMODEL],        g_xl[MROWS * DMODEL];
__device__ hf16 g_wqt_h[(size_t)3*DMODEL*DMODEL];
__device__ hf16 g_wot_h[(size_t)DMODEL*DMODEL];
__device__ hf16 g_qkvh[MROWS * 3*DMODEL],    g_qkvl[MROWS * 3*DMODEL];
__device__ hf16 g_ctxh[MROWS * DMODEL],      g_ctxl[MROWS * DMODEL];

// ---------------- helpers ----------------
__device__ __forceinline__ uint32_t sptr(const void* p) {
    return (uint32_t)__cvta_generic_to_shared(p);
}
__device__ __forceinline__ void cpa16(void* s, const void* g) {
    asm volatile("cp.async.cg.shared.global [%0], [%1], 16;\n" :: "r"(sptr(s)), "l"(g));
}
__device__ __forceinline__ void cpa16s(uint32_t s, const void* g) {
    asm volatile("cp.async.cg.shared.global [%0], [%1], 16;\n" :: "r"(s), "l"(g));
}
__device__ __forceinline__ void cpcommit() { asm volatile("cp.async.commit_group;\n"); }
__device__ __forceinline__ void cpwait0()  { asm volatile("cp.async.wait_group 0;\n"); }
__device__ __forceinline__ void cpwait1()  { asm volatile("cp.async.wait_group 1;\n"); }

__device__ __forceinline__ void ldsm4(uint32_t* r, const void* p) {
    asm volatile("ldmatrix.sync.aligned.m8n8.x4.shared.b16 {%0,%1,%2,%3}, [%4];\n"
        : "=r"(r[0]), "=r"(r[1]), "=r"(r[2]), "=r"(r[3]) : "r"(sptr(p)));
}
__device__ __forceinline__ void ldsm4s(uint32_t* r, uint32_t a) {
    asm volatile("ldmatrix.sync.aligned.m8n8.x4.shared.b16 {%0,%1,%2,%3}, [%4];\n"
        : "=r"(r[0]), "=r"(r[1]), "=r"(r[2]), "=r"(r[3]) : "r"(a));
}
__device__ __forceinline__ void ldsm4t(uint32_t* r, const void* p) {
    asm volatile("ldmatrix.sync.aligned.m8n8.x4.trans.shared.b16 {%0,%1,%2,%3}, [%4];\n"
        : "=r"(r[0]), "=r"(r[1]), "=r"(r[2]), "=r"(r[3]) : "r"(sptr(p)));
}
__device__ __forceinline__ void ldsm2s(uint32_t* r, uint32_t a) {
    asm volatile("ldmatrix.sync.aligned.m8n8.x2.shared.b16 {%0,%1}, [%2];\n"
        : "=r"(r[0]), "=r"(r[1]) : "r"(a));
}
// fp16 MMA, fp32 accum
__device__ __forceinline__ void mma16816(float* c, const uint32_t* a, const uint32_t* b) {
    asm volatile("mma.sync.aligned.m16n8k16.row.col.f32.f16.f16.f32 "
        "{%0,%1,%2,%3}, {%4,%5,%6,%7}, {%8,%9}, {%0,%1,%2,%3};\n"
        : "+f"(c[0]), "+f"(c[1]), "+f"(c[2]), "+f"(c[3])
        : "r"(a[0]), "r"(a[1]), "r"(a[2]), "r"(a[3]), "r"(b[0]), "r"(b[1]));
}
// rn-split fp16 (converters)
__device__ __forceinline__ void split1(float v, hf16& h, hf16& l) {
    h = __float2half_rn(v);
    l = __float2half_rn(v - __half2float(h));
}
__device__ __forceinline__ uint32_t pack2(hf16 lo, hf16 hi) {
    __half2 t = __halves2half2(lo, hi);
    return *reinterpret_cast<uint32_t*>(&t);
}
__device__ __forceinline__ void split_pack2_rn(float v0, float v1, uint32_t& ph, uint32_t& pl) {
    hf16 h0,l0,h1,l1;
    split1(v0,h0,l0); split1(v1,h1,l1);
    ph = pack2(h0,h1);
    pl = pack2(l0,l1);
}
// fast fp16 split: h = rn(v), l = v - h (exact); packed with cvt.rn.f16x2
__device__ __forceinline__ void split_pack2(float v0, float v1, uint32_t& ph, uint32_t& pl) {
    asm("cvt.rn.f16x2.f32 %0, %1, %2;" : "=r"(ph) : "f"(v1), "f"(v0));  // lo=v0, hi=v1
    __half2 hp = *reinterpret_cast<__half2*>(&ph);
    float l0 = v0 - __low2float(hp);
    float l1 = v1 - __high2float(hp);
    asm("cvt.rn.f16x2.f32 %0, %1, %2;" : "=r"(pl) : "f"(l1), "f"(l0));
}
// SW64 swizzle: XOR bits[5:4] with bits[8:7] (64B rows)
__device__ __forceinline__ uint32_t sw64(uint32_t off) {
    return off ^ ((off >> 3) & 0x30);
}
// exp(s*0.125) = 2^(s*YS) via magic rounding + degree-5 poly, Y_SCALE folded in.
#define Y_SCALE 0.18033688011112042f   // 0.125 * log2(e)
__device__ __forceinline__ float fexp2s(float s) {
    float t = fmaf(s, Y_SCALE, 12582912.f);
    float n = t - 12582912.f;
    float f = fmaf(s, Y_SCALE, -n);
    float p = 0.00133335581f;
    p = fmaf(p, f, 0.00961812911f);
    p = fmaf(p, f, 0.05550410866f);
    p = fmaf(p, f, 0.24022650696f);
    p = fmaf(p, f, 0.69314718056f);
    p = fmaf(p, f, 1.0f);
    int e = (__float_as_int(t) - 0x4B400000 + 127) << 23;
    return __int_as_float(e) * p;
}

// ---------------- converters ----------------
__global__ void split_kernel(const float* __restrict__ in,
                             hf16* __restrict__ oh, hf16* __restrict__ ol, int n4)
{
    int i = blockIdx.x * blockDim.x + threadIdx.x;
    if (i >= n4) return;
    float4 v = ((const float4*)in)[i];
    uint32_t ph0, pl0, ph1, pl1;
    split_pack2_rn(v.x, v.y, ph0, pl0);
    split_pack2_rn(v.z, v.w, ph1, pl1);
    ((uint32_t*)oh)[2*i]   = ph0;
    ((uint32_t*)oh)[2*i+1] = ph1;
    ((uint32_t*)ol)[2*i]   = pl0;
    ((uint32_t*)ol)[2*i+1] = pl1;
}

// in: [K][N] fp32 -> out: [N][K] fp16 (hi only; B operands need no lo)
__global__ void transpose_half(const float* __restrict__ in,
                               hf16* __restrict__ oh, int K, int N)
{
    __shared__ float t[32][33];
    int k0 = blockIdx.y * 32, n0 = blockIdx.x * 32;
    int tx = threadIdx.x, ty = threadIdx.y;
#pragma unroll
    for (int i = 0; i < 4; i++)
        t[ty + 8*i][tx] = in[(size_t)(k0 + ty + 8*i) * N + n0 + tx];
    __syncthreads();
#pragma unroll
    for (int i = 0; i < 4; i++) {
        float v = t[tx][ty + 8*i];
        oh[(size_t)(n0 + ty + 8*i) * K + k0 + tx] = __float2half_rn(v);
    }
}

// ---------------- GEMM (fp16, 2-term: Ah*Bh + Al*Bh), 3-stage, 2 CTAs/SM ----
// Per stage: Ah, Al, Bh buffers, each 128x32 fp16 = 8KB, SW64 swizzled.
#define GSTG 24576
__global__ __launch_bounds__(256, 2)
void mma_gemm(const hf16* __restrict__ Ah, const hf16* __restrict__ Al,
              const hf16* __restrict__ Bh,
              float* __restrict__ Cf, hf16* __restrict__ Ch, hf16* __restrict__ Cl,
              const float* __restrict__ bias, int M, int N, int K)
{
    const uint32_t smbase = (sptr(dynsm) + 1023u) & ~1023u;

    const int tid  = threadIdx.x;
    const int lane = tid & 31, wid = tid >> 5;
    const int mw = wid >> 2, nw = wid & 3;
    const int bm = blockIdx.y * 128, bn = blockIdx.x * 128;

    float acc[4][4][4];
#pragma unroll
    for (int a = 0; a < 4; a++)
#pragma unroll
        for (int b = 0; b < 4; b++)
#pragma unroll
            for (int c = 0; c < 4; c++) acc[a][b][c] = 0.f;

    auto stage = [&](int st, int kc) {
        const int k0 = kc * 32;
        const uint32_t sb = smbase + st * GSTG;
#pragma unroll
        for (int i = 0; i < 2; i++) {
            int s = tid + i * 256;
            int r = s >> 2, c = (s & 3) * 8;
            uint32_t off = sw64((uint32_t)(r * 64 + c * 2));
            size_t ga = (size_t)(bm + r) * K + k0 + c;
            size_t gb = (size_t)(bn + r) * K + k0 + c;
            cpa16s(sb + off,         Ah + ga);
            cpa16s(sb +  8192 + off, Al + ga);
            cpa16s(sb + 16384 + off, Bh + gb);
        }
        cpcommit();
    };

    const int NT = K / 32;
    stage(0, 0);
    stage(1, 1);

    for (int kt = 0; kt < NT; kt++) {
        const uint32_t sb = smbase + (kt % 3) * GSTG;
        if (kt + 1 < NT) cpwait1(); else cpwait0();
        __syncthreads();
        if (kt + 2 < NT) stage((kt + 2) % 3, kt + 2);

#pragma unroll
        for (int ks = 0; ks < 2; ks++) {
            uint32_t afh[4][4], afl[4][4], bfh[4][2];
#pragma unroll
            for (int mf = 0; mf < 4; mf++) {
                int row = mw*64 + mf*16 + (lane & 15);
                int col = ks*16 + (lane >> 4) * 8;
                uint32_t off = sw64((uint32_t)(row * 64 + col * 2));
                ldsm4s(afh[mf], sb + off);
                ldsm4s(afl[mf], sb + 8192 + off);
            }
#pragma unroll
            for (int nf = 0; nf < 4; nf++) {
                int li = lane & 15;
                int row = nw*32 + nf*8 + (li & 7);
                int col = ks*16 + (li >> 3) * 8;
                uint32_t off = sw64((uint32_t)(row * 64 + col * 2));
                ldsm2s(bfh[nf], sb + 16384 + off);
            }
#pragma unroll
            for (int mf = 0; mf < 4; mf++)
#pragma unroll
                for (int nf = 0; nf < 4; nf++)
                    mma16816(acc[mf][nf], afh[mf], bfh[nf]);
#pragma unroll
            for (int mf = 0; mf < 4; mf++)
#pragma unroll
                for (int nf = 0; nf < 4; nf++)
                    mma16816(acc[mf][nf], afl[mf], bfh[nf]);
        }
    }

#pragma unroll
    for (int mf = 0; mf < 4; mf++)
#pragma unroll
        for (int nf = 0; nf < 4; nf++)
#pragma unroll
            for (int c = 0; c < 2; c++) {
                int row = bm + mw*64 + mf*16 + (lane >> 2) + c*8;
                int col = bn + nw*32 + nf*8  + 2*(lane & 3);
                float v0 = acc[mf][nf][2*c+0];
                float v1 = acc[mf][nf][2*c+1];
                if (bias) { v0 += bias[col]; v1 += bias[col+1]; }
                if (Cf) *(float2*)&Cf[(size_t)row * N + col] = make_float2(v0, v1);
                if (Ch) {
                    uint32_t ph, pl;
                    split_pack2(v0, v1, ph, pl);
                    *(uint32_t*)&Ch[(size_t)row * N + col] = ph;
                    *(uint32_t*)&Cl[(size_t)row * N + col] = pl;
                }
            }
}

// ---------------- one-pass attention (fp16 2-term), 2 CTAs/SM --------------
// Q (A op): hi/lo split; K,V (B ops): hi only -> KV traffic halves.
#define KB2 4608   // 64*72 halfs per K/V stage
__global__ __launch_bounds__(256, 2)
void attn_one(const hf16* __restrict__ qh, const hf16* __restrict__ ql,
              const int* __restrict__ mask,
              float* __restrict__ attn,
              hf16* __restrict__ ctxh, hf16* __restrict__ ctxl)
{
    char* sm = dynsm;
    hf16*  sQh  = (hf16*)sm;                    // 128*72
    hf16*  sQl  = (hf16*)(sm + 18432);
    hf16*  sK   = (hf16*)(sm + 36864);          // [2 st][64*72]
    hf16*  sV   = (hf16*)(sm + 55296);          // [2 st][64*72]
    int*   smask = (int*)(sm + 73728);          // [2][64]
    float* lrec  = (float*)(sm + 74240);        // [128]

    const int tid = threadIdx.x, lane = tid & 31, w = tid >> 5;
    const int q0 = blockIdx.x * QT;
    const int bh = blockIdx.y, b = bh >> 4, h = bh & 15;
    const size_t RS = 3 * DMODEL;

    for (int s = tid; s < 1024; s += 256) {
        int r = s >> 3, c = (s & 7) * 8;
        size_t g = (size_t)(b*SEQ + q0 + r) * RS + h*DHEAD + c;
        cpa16(&sQh[r*72 + c], qh + g);
        cpa16(&sQl[r*72 + c], ql + g);
    }
    cpcommit();

    auto stageKV = [&](int st, int kt) {
        int k0 = kt * 64;
        if (tid < 64) smask[st*64 + tid] = mask[b*SEQ + k0 + tid];
#pragma unroll
        for (int i = 0; i < 2; i++) {
            int s = tid + i * 256;
            int r = s >> 3, c = (s & 7) * 8;
            size_t gk = (size_t)(b*SEQ + k0 + r) * RS + DMODEL + h*DHEAD + c;
            size_t gv = gk + DMODEL;
            cpa16(&sK[st*KB2 + r*72 + c], qh + gk);
            cpa16(&sV[st*KB2 + r*72 + c], qh + gv);
        }
        cpcommit();
    };

    stageKV(0, 0);
    cpwait0();
    __syncthreads();

    float oacc[8][4];
#pragma unroll
    for (int nf = 0; nf < 8; nf++)
#pragma unroll
        for (int c = 0; c < 4; c++) oacc[nf][c] = 0.f;
    float rs0 = 0.f, rs1 = 0.f;

    const int rlo = lane >> 2, qq = lane & 3;
    const int g8 = lane >> 3;
    const size_t abase = ((size_t)bh * SEQ + q0) * SEQ;

    for (int kt = 0; kt < 16; kt++) {
        int st = kt & 1;
        if (kt) { cpwait0(); __syncthreads(); }
        if (kt + 1 < 16) stageKV(st ^ 1, kt + 1);

        float sacc[8][4];
#pragma unroll
        for (int nf = 0; nf < 8; nf++)
#pragma unroll
            for (int c = 0; c < 4; c++) sacc[nf][c] = 0.f;

#pragma unroll
        for (int ks = 0; ks < 4; ks++) {
            uint32_t q4h[4], q4l[4];
            int qoff = (w*16 + (lane & 15)) * 72 + ks*16 + (lane >> 4) * 8;
            ldsm4(q4h, &sQh[qoff]);
            ldsm4(q4l, &sQl[qoff]);
#pragma unroll
            for (int p = 0; p < 4; p++) {
                int off = (p*16 + (g8 & 1)*8 + (lane & 7)) * 72 + ks*16 + (g8 >> 1) * 8;
                uint32_t r4[4];
                ldsm4(r4, &sK[st*KB2 + off]);
                uint32_t b0[2] = {r4[0], r4[2]}, b1[2] = {r4[1], r4[3]};
                mma16816(sacc[2*p],   q4h, b0);
                mma16816(sacc[2*p+1], q4h, b1);
                mma16816(sacc[2*p],   q4l, b0);
                mma16816(sacc[2*p+1], q4l, b1);
            }
        }

#pragma unroll
        for (int nf = 0; nf < 8; nf++) {
            int c0i = nf*8 + 2*qq;
            int m0 = smask[st*64 + c0i];
            int m1 = smask[st*64 + c0i + 1];
            float e0 = m0 ? fexp2s(sacc[nf][0]) : 0.f;
            float e1 = m1 ? fexp2s(sacc[nf][1]) : 0.f;
            float e2 = m0 ? fexp2s(sacc[nf][2]) : 0.f;
            float e3 = m1 ? fexp2s(sacc[nf][3]) : 0.f;
            sacc[nf][0] = e0; sacc[nf][1] = e1; sacc[nf][2] = e2; sacc[nf][3] = e3;
            rs0 += e0 + e1;
            rs1 += e2 + e3;
            size_t a0 = abase + (size_t)(w*16 + rlo) * SEQ + kt*64 + c0i;
            *(float2*)&attn[a0]           = make_float2(e0, e1);
            *(float2*)&attn[a0 + 8*SEQ]   = make_float2(e2, e3);
        }

#pragma unroll
        for (int pk = 0; pk < 4; pk++) {
            uint32_t ah[4], al[4];
            split_pack2(sacc[2*pk][0],   sacc[2*pk][1],   ah[0], al[0]);
            split_pack2(sacc[2*pk][2],   sacc[2*pk][3],   ah[1], al[1]);
            split_pack2(sacc[2*pk+1][0], sacc[2*pk+1][1], ah[2], al[2]);
            split_pack2(sacc[2*pk+1][2], sacc[2*pk+1][3], ah[3], al[3]);
#pragma unroll
            for (int p = 0; p < 4; p++) {
                int off = (pk*16 + (g8 & 1)*8 + (lane & 7)) * 72 + (2*p + (g8 >> 1)) * 8;
                uint32_t r4[4];
                ldsm4t(r4, &sV[st*KB2 + off]);
                uint32_t v0[2] = {r4[0], r4[1]}, v1[2] = {r4[2], r4[3]};
                mma16816(oacc[2*p],   ah, v0);
                mma16816(oacc[2*p+1], ah, v1);
                mma16816(oacc[2*p],   al, v0);
                mma16816(oacc[2*p+1], al, v1);
            }
        }
    }

    rs0 += __shfl_xor_sync(0xffffffffu, rs0, 1);
    rs0 += __shfl_xor_sync(0xffffffffu, rs0, 2);
    rs1 += __shfl_xor_sync(0xffffffffu, rs1, 1);
    rs1 += __shfl_xor_sync(0xffffffffu, rs1, 2);
    float ri0 = 1.f / rs0, ri1 = 1.f / rs1;
    if ((lane & 3) == 0) {
        lrec[w*16 + rlo]     = ri0;
        lrec[w*16 + rlo + 8] = ri1;
    }

    const size_t row0 = (size_t)(b*SEQ + q0 + w*16 + rlo);
#pragma unroll
    for (int nf = 0; nf < 8; nf++) {
        int col = h*DHEAD + nf*8 + 2*qq;
        uint32_t hp, lp;
        split_pack2(oacc[nf][0] * ri0, oacc[nf][1] * ri0, hp, lp);
        *(uint32_t*)&ctxh[row0*DMODEL + col] = hp;
        *(uint32_t*)&ctxl[row0*DMODEL + col] = lp;
        split_pack2(oacc[nf][2] * ri1, oacc[nf][3] * ri1, hp, lp);
        *(uint32_t*)&ctxh[(row0+8)*DMODEL + col] = hp;
        *(uint32_t*)&ctxl[(row0+8)*DMODEL + col] = lp;
    }

    __syncthreads();   // lrec visible + all attn stores in-block visible

    // normalize this block's attn region (L2-hot re-read)
    for (int s = tid; s < QT * 256; s += 256) {
        int r = s >> 8, c = (s & 255) * 4;
        float sc = lrec[r];
        float4* p = (float4*)(attn + abase + (size_t)r * SEQ + c);
        float4 v = *p;
        v.x *= sc; v.y *= sc; v.z *= sc; v.w *= sc;
        *p = v;
    }
}

// ---------------- launcher ----------------
extern "C" void kernel_launch(void* const* d_in, const int* in_sizes, int n_in,
                              void* d_out, int out_size)
{
    const float* x     = (const float*)d_in[0];
    const int*   mask  = (const int*)d_in[1];
    const float* w_qkv = (const float*)d_in[2];
    const float* w_out = (const float*)d_in[3];
    const float* b_out = (const float*)d_in[4];

    float* out  = (float*)d_out;
    float* attn = out + MROWS * DMODEL;

    hf16 *xh, *xl, *wqh, *woh, *qkvh, *qkvl, *ctxh, *ctxl;
    cudaGetSymbolAddress((void**)&xh,  g_xh);  cudaGetSymbolAddress((void**)&xl,  g_xl);
    cudaGetSymbolAddress((void**)&wqh, g_wqt_h);
    cudaGetSymbolAddress((void**)&woh, g_wot_h);
    cudaGetSymbolAddress((void**)&qkvh, g_qkvh); cudaGetSymbolAddress((void**)&qkvl, g_qkvl);
    cudaGetSymbolAddress((void**)&ctxh, g_ctxh); cudaGetSymbolAddress((void**)&ctxl, g_ctxl);

    cudaFuncSetAttribute(mma_gemm, cudaFuncAttributeMaxDynamicSharedMemorySize, 74752);
    cudaFuncSetAttribute(attn_one, cudaFuncAttributeMaxDynamicSharedMemorySize, 74752);

    {
        int n4 = (int)(MROWS * DMODEL / 4);
        split_kernel<<<(n4 + 255) / 256, 256>>>(x, xh, xl, n4);
    }
    transpose_half<<<dim3(3*DMODEL/32, DMODEL/32), dim3(32,8)>>>(w_qkv, wqh, DMODEL, 3*DMODEL);
    transpose_half<<<dim3(DMODEL/32,   DMODEL/32), dim3(32,8)>>>(w_out, woh, DMODEL, DMODEL);

    mma_gemm<<<dim3(3*DMODEL/128, (int)(MROWS/128)), 256, 74752>>>(
        xh, xl, wqh, nullptr, qkvh, qkvl, nullptr,
        (int)MROWS, 3*DMODEL, DMODEL);

    attn_one<<<dim3(SEQ/QT, BDIM*NHEAD), 256, 74752>>>(
        qkvh, qkvl, mask, attn, ctxh, ctxl);

    mma_gemm<<<dim3(DMODEL/128, (int)(MROWS/128)), 256, 74752>>>(
        ctxh, ctxl, woh, out, nullptr, nullptr, b_out,
        (int)MROWS, DMODEL, DMODEL);
}